// round 1
// baseline (speedup 1.0000x reference)
#include <cuda_runtime.h>
#include <cuda_bf16.h>
#include <math.h>

// ---------------- problem constants ----------------
#define NROWS   131072
#define DIM     256
#define NCODES  1024
#define NSTAGES 8
#define EPSF    1e-12f

// ---------------- scratch (__device__ globals; no allocs allowed) ----------
__device__ float g_residual[(size_t)NROWS * DIM];   // ~134 MB
__device__ int   g_idx[NROWS];
__device__ int   g_presence[NSTAGES * NCODES];
__device__ float g_cnorm[NCODES];

// ---------------- tiling ----------------
#define BM 128
#define BN 128
#define BK 32
#define TM 8
#define TN 8
// 256 threads: tx = tid & 15 (codes), ty = tid >> 4 (rows)

// ============================================================
// residual = input (float4 copy)
// ============================================================
__global__ void copy_kernel(const float* __restrict__ src) {
    int i = blockIdx.x * blockDim.x + threadIdx.x;   // float4 index
    const float4* s = (const float4*)src;
    float4* d = (float4*)g_residual;
    d[i] = s[i];
}

__global__ void zero_presence_kernel() {
    int i = blockIdx.x * blockDim.x + threadIdx.x;
    if (i < NSTAGES * NCODES) g_presence[i] = 0;
}

// ============================================================
// cnorm[j] = sum_d C[j][d]^2   (one warp per code)
// ============================================================
__global__ void cnorm_kernel(const float* __restrict__ C) {
    int code = blockIdx.x;
    int lane = threadIdx.x;                // 0..31
    const float4* c = (const float4*)(C + (size_t)code * DIM);
    float s = 0.f;
    #pragma unroll
    for (int t = 0; t < 2; t++) {
        float4 v = c[lane + t * 32];
        s += v.x * v.x + v.y * v.y + v.z * v.z + v.w * v.w;
    }
    #pragma unroll
    for (int off = 16; off > 0; off >>= 1)
        s += __shfl_xor_sync(0xffffffffu, s, off);
    if (lane == 0) g_cnorm[code] = s;
}

// ============================================================
// fused GEMM + argmin:
//   score[r][j] = cnorm[j] - 2 * dot(residual[r], C[j]);  idx[r] = argmin_j
// ============================================================
__global__ void __launch_bounds__(256, 2)
argmin_kernel(const float* __restrict__ C) {
    __shared__ float As[BK][BM + 4];   // [k][row]
    __shared__ float Bs[BK][BN + 4];   // [k][code]

    const int tid = threadIdx.x;
    const int tx = tid & 15;
    const int ty = tid >> 4;
    const int row0 = blockIdx.x * BM;

    float best[TM];
    int   bidx[TM];
    #pragma unroll
    for (int i = 0; i < TM; i++) { best[i] = INFINITY; bidx[i] = 0; }

    for (int cc = 0; cc < NCODES / BN; ++cc) {
        float acc[TM][TN];
        #pragma unroll
        for (int i = 0; i < TM; i++)
            #pragma unroll
            for (int j = 0; j < TN; j++) acc[i][j] = 0.f;

        for (int kt = 0; kt < DIM / BK; ++kt) {
            // cooperative transposed loads: 4096 floats each tile
            #pragma unroll
            for (int l = 0; l < 4; l++) {
                int e  = tid + l * 256;          // 0..1023
                int r  = e >> 3;                 // 0..127
                int kv = (e & 7) * 4;            // 0,4,...,28
                float4 v = *(const float4*)&g_residual[(size_t)(row0 + r) * DIM + kt * BK + kv];
                As[kv + 0][r] = v.x; As[kv + 1][r] = v.y;
                As[kv + 2][r] = v.z; As[kv + 3][r] = v.w;
                float4 w = *(const float4*)&C[(size_t)(cc * BN + r) * DIM + kt * BK + kv];
                Bs[kv + 0][r] = w.x; Bs[kv + 1][r] = w.y;
                Bs[kv + 2][r] = w.z; Bs[kv + 3][r] = w.w;
            }
            __syncthreads();

            #pragma unroll
            for (int k = 0; k < BK; k++) {
                float a[TM], b[TN];
                *(float4*)&a[0] = *(const float4*)&As[k][ty * TM];
                *(float4*)&a[4] = *(const float4*)&As[k][ty * TM + 4];
                *(float4*)&b[0] = *(const float4*)&Bs[k][tx * TN];
                *(float4*)&b[4] = *(const float4*)&Bs[k][tx * TN + 4];
                #pragma unroll
                for (int i = 0; i < TM; i++)
                    #pragma unroll
                    for (int j = 0; j < TN; j++)
                        acc[i][j] = fmaf(a[i], b[j], acc[i][j]);
            }
            __syncthreads();
        }

        // fold this code chunk into running argmin
        #pragma unroll
        for (int j = 0; j < TN; j++) {
            int code = cc * BN + tx * TN + j;
            float cn = __ldg(&g_cnorm[code]);
            #pragma unroll
            for (int i = 0; i < TM; i++) {
                float s = fmaf(-2.f, acc[i][j], cn);
                if (s < best[i]) { best[i] = s; bidx[i] = code; }
            }
        }
    }

    // reduce across the 16 tx lanes (same-ty lanes are contiguous 16-lane groups)
    #pragma unroll
    for (int i = 0; i < TM; i++) {
        float s = best[i];
        int   bi = bidx[i];
        #pragma unroll
        for (int off = 8; off >= 1; off >>= 1) {
            float s2 = __shfl_xor_sync(0xffffffffu, s, off);
            int   i2 = __shfl_xor_sync(0xffffffffu, bi, off);
            if (s2 < s || (s2 == s && i2 < bi)) { s = s2; bi = i2; }
        }
        if (tx == 0) g_idx[row0 + ty * TM + i] = bi;
    }
}

// ============================================================
// residual[r] -= C[idx[r]];  presence[stage][idx[r]] = 1
// one warp per row
// ============================================================
__global__ void update_kernel(const float* __restrict__ C, int stage) {
    int w = (blockIdx.x * blockDim.x + threadIdx.x) >> 5;  // row
    int lane = threadIdx.x & 31;
    if (w >= NROWS) return;
    int code = g_idx[w];
    if (lane == 0) g_presence[stage * NCODES + code] = 1;  // benign race
    const float4* q = (const float4*)(C + (size_t)code * DIM);
    float4* r = (float4*)(g_residual + (size_t)w * DIM);
    #pragma unroll
    for (int t = 0; t < 2; t++) {
        int e = lane + t * 32;
        float4 qq = q[e];
        float4 rr = r[e];
        rr.x -= qq.x; rr.y -= qq.y; rr.z -= qq.z; rr.w -= qq.w;
        r[e] = rr;
    }
}

// ============================================================
// out[r] = input + (||residual_r|| / ||noise_r|| + EPS) * noise   (train)
//        = input - residual                                        (eval)
// one warp per row
// ============================================================
__global__ void finalize_kernel(const float* __restrict__ inp,
                                const float* __restrict__ noise,
                                const int* __restrict__ train_mode,
                                float* __restrict__ out) {
    int w = (blockIdx.x * blockDim.x + threadIdx.x) >> 5;
    int lane = threadIdx.x & 31;
    if (w >= NROWS) return;
    int tm = *train_mode;
    const float4* rp = (const float4*)(g_residual + (size_t)w * DIM);
    const float4* np = (const float4*)(noise + (size_t)w * DIM);
    const float4* ip = (const float4*)(inp + (size_t)w * DIM);
    float4* op = (float4*)(out + (size_t)w * DIM);

    float4 rv[2], nv[2];
    float se = 0.f, sn = 0.f;
    #pragma unroll
    for (int t = 0; t < 2; t++) {
        rv[t] = rp[lane + t * 32];
        nv[t] = np[lane + t * 32];
        se += rv[t].x * rv[t].x + rv[t].y * rv[t].y + rv[t].z * rv[t].z + rv[t].w * rv[t].w;
        sn += nv[t].x * nv[t].x + nv[t].y * nv[t].y + nv[t].z * nv[t].z + nv[t].w * nv[t].w;
    }
    #pragma unroll
    for (int off = 16; off > 0; off >>= 1) {
        se += __shfl_xor_sync(0xffffffffu, se, off);
        sn += __shfl_xor_sync(0xffffffffu, sn, off);
    }

    if (tm) {
        float f = sqrtf(se) / sqrtf(sn) + EPSF;
        #pragma unroll
        for (int t = 0; t < 2; t++) {
            float4 iv = ip[lane + t * 32];
            float4 o;
            o.x = iv.x + f * nv[t].x; o.y = iv.y + f * nv[t].y;
            o.z = iv.z + f * nv[t].z; o.w = iv.w + f * nv[t].w;
            op[lane + t * 32] = o;
        }
    } else {
        #pragma unroll
        for (int t = 0; t < 2; t++) {
            float4 iv = ip[lane + t * 32];
            float4 o;
            o.x = iv.x - rv[t].x; o.y = iv.y - rv[t].y;
            o.z = iv.z - rv[t].z; o.w = iv.w - rv[t].w;
            op[lane + t * 32] = o;
        }
    }
}

// ============================================================
// used tail: out[N*D + i] = float(used_in[i] + presence[i])
// ============================================================
__global__ void used_kernel(const int* __restrict__ used_in,
                            float* __restrict__ out_tail) {
    int i = blockIdx.x * blockDim.x + threadIdx.x;
    if (i < NSTAGES * NCODES)
        out_tail[i] = (float)(used_in[i] + g_presence[i]);
}

// ============================================================
// launch
// ============================================================
extern "C" void kernel_launch(void* const* d_in, const int* in_sizes, int n_in,
                              void* d_out, int out_size) {
    const float* input     = (const float*)d_in[0];   // [N, 256]
    const float* codebooks = (const float*)d_in[1];   // [8, 1024, 256]
    const float* noise     = (const float*)d_in[2];   // [N, 256]
    const int*   used_in   = (const int*)d_in[3];     // [8, 1024]
    const int*   train_mod = (const int*)d_in[4];     // scalar
    float* out = (float*)d_out;

    // residual = input; presence = 0
    copy_kernel<<<(NROWS * DIM / 4) / 256, 256>>>(input);
    zero_presence_kernel<<<(NSTAGES * NCODES + 255) / 256, 256>>>();

    for (int s = 0; s < NSTAGES; ++s) {
        const float* Cs = codebooks + (size_t)s * NCODES * DIM;
        cnorm_kernel<<<NCODES, 32>>>(Cs);
        argmin_kernel<<<NROWS / BM, 256>>>(Cs);
        update_kernel<<<(NROWS * 32) / 256, 256>>>(Cs, s);
    }

    finalize_kernel<<<(NROWS * 32) / 256, 256>>>(input, noise, train_mod, out);

    if (out_size >= NROWS * DIM + NSTAGES * NCODES) {
        used_kernel<<<(NSTAGES * NCODES + 255) / 256, 256>>>(used_in,
                                                             out + (size_t)NROWS * DIM);
    }
}

// round 3
// speedup vs baseline: 7.5505x; 7.5505x over previous
#include <cuda_runtime.h>
#include <cuda_bf16.h>
#include <math.h>
#include <stdint.h>

// ---------------- problem constants ----------------
#define NROWS   131072
#define DIM     256
#define NCODES  1024
#define NSTAGES 8
#define EPSF    1e-12f

#define ROWS_CTA 128

// ---------------- smem layout (bytes) ----------------
#define A_STRIDE 264                    // bf16 elems per A row (128B+16B skew)
#define SM_A     0                      // 128 x 264 bf16 = 67584
#define B_STRIDE 72                     // bf16 elems per B row (16B skew)
#define B_TILE   18432                  // 128 codes x 72 elems x 2B
#define SM_B     67584                  // two tiles: 36864
#define SM_CN    104448                 // float[1024]
#define SM_REDV  108544                 // float[4][128]
#define SM_REDI  110592                 // int[4][128]
#define SM_IDX   112640                 // int[128]
#define SMEM_TOTAL 113152

// ---------------- device globals (no allocs allowed) ----------------
__device__ float g_res[(size_t)NROWS * DIM];                    // 134 MB residual
__device__ __nv_bfloat16 g_cb[(size_t)NSTAGES * NCODES * DIM];  // 4 MB bf16 codebooks
__device__ float g_cnorm[NSTAGES * NCODES];
__device__ int   g_presence[NSTAGES * NCODES];

// ================= helpers =================
__device__ __forceinline__ uint32_t smem_u32(const void* p) {
    uint32_t a;
    asm("{ .reg .u64 t; cvta.to.shared.u64 t, %1; cvt.u32.u64 %0, t; }" : "=r"(a) : "l"(p));
    return a;
}

#define CP_COMMIT asm volatile("cp.async.commit_group;" ::: "memory")
#define CP_WAIT1  asm volatile("cp.async.wait_group 1;" ::: "memory")
#define CP_WAIT0  asm volatile("cp.async.wait_group 0;" ::: "memory")

__device__ __forceinline__ void ldmx4(uint32_t* r, uint32_t addr) {
    asm volatile("ldmatrix.sync.aligned.m8n8.x4.shared.b16 {%0,%1,%2,%3}, [%4];"
                 : "=r"(r[0]), "=r"(r[1]), "=r"(r[2]), "=r"(r[3]) : "r"(addr));
}
__device__ __forceinline__ void ldmx4t(uint32_t* r, uint32_t addr) {
    asm volatile("ldmatrix.sync.aligned.m8n8.x4.trans.shared.b16 {%0,%1,%2,%3}, [%4];"
                 : "=r"(r[0]), "=r"(r[1]), "=r"(r[2]), "=r"(r[3]) : "r"(addr));
}
__device__ __forceinline__ void mma16816(float* c, const uint32_t* a, uint32_t b0, uint32_t b1) {
    asm volatile("mma.sync.aligned.m16n8k16.row.col.f32.bf16.bf16.f32 "
                 "{%0,%1,%2,%3}, {%4,%5,%6,%7}, {%8,%9}, {%0,%1,%2,%3};"
                 : "+f"(c[0]), "+f"(c[1]), "+f"(c[2]), "+f"(c[3])
                 : "r"(a[0]), "r"(a[1]), "r"(a[2]), "r"(a[3]), "r"(b0), "r"(b1));
}

// cp.async a B tile: stage s, flat tile t (nsc = t>>2, kb = t&3):
// 128 codes x 64 dims bf16 -> smem [code][72] (16B skew rows)
__device__ __forceinline__ void cp_b(int s, int t, uint32_t dst, int tid) {
    int nsc = t >> 2, kb = t & 3;
    const char* gbase = (const char*)(g_cb + ((size_t)(s * NCODES + nsc * 128) * DIM) + kb * 64);
    #pragma unroll
    for (int i = 0; i < 4; i++) {
        int e = tid + (i << 8);
        int c = e >> 3, j = e & 7;
        uint32_t d = dst + c * 144 + j * 16;
        const char* src = gbase + (size_t)c * 512 + j * 16;
        asm volatile("cp.async.cg.shared.global [%0], [%1], 16;" :: "r"(d), "l"(src));
    }
}

// ================= prep: bf16 codebooks + cnorms =================
__global__ void prep_kernel(const float* __restrict__ cb) {
    int cid  = blockIdx.x * 8 + (threadIdx.x >> 5);
    int lane = threadIdx.x & 31;
    const float4* p = (const float4*)(cb + (size_t)cid * DIM);
    float4 v0 = p[lane * 2];
    float4 v1 = p[lane * 2 + 1];
    float s = v0.x*v0.x + v0.y*v0.y + v0.z*v0.z + v0.w*v0.w
            + v1.x*v1.x + v1.y*v1.y + v1.z*v1.z + v1.w*v1.w;
    #pragma unroll
    for (int o = 16; o > 0; o >>= 1) s += __shfl_xor_sync(0xffffffffu, s, o);
    if (lane == 0) g_cnorm[cid] = s;
    __nv_bfloat162 b0 = __floats2bfloat162_rn(v0.x, v0.y);
    __nv_bfloat162 b1 = __floats2bfloat162_rn(v0.z, v0.w);
    __nv_bfloat162 b2 = __floats2bfloat162_rn(v1.x, v1.y);
    __nv_bfloat162 b3 = __floats2bfloat162_rn(v1.z, v1.w);
    uint4 u;
    u.x = *(uint32_t*)&b0; u.y = *(uint32_t*)&b1; u.z = *(uint32_t*)&b2; u.w = *(uint32_t*)&b3;
    ((uint4*)g_cb)[(size_t)cid * 32 + lane] = u;
}

__global__ void zero_presence_kernel() {
    int i = blockIdx.x * blockDim.x + threadIdx.x;
    if (i < NSTAGES * NCODES) g_presence[i] = 0;
}

__global__ void used_kernel(const int* __restrict__ used_in, float* __restrict__ out_tail) {
    int i = blockIdx.x * blockDim.x + threadIdx.x;
    if (i < NSTAGES * NCODES) out_tail[i] = (float)(used_in[i] + g_presence[i]);
}

// ================= main fused kernel =================
__global__ void __launch_bounds__(256, 2)
rvq_main(const float* __restrict__ input, const float* __restrict__ cbf32,
         const float* __restrict__ noise, const int* __restrict__ trainp,
         float* __restrict__ out) {
    extern __shared__ char smem[];
    const uint32_t sb = smem_u32(smem);
    float* cnS  = (float*)(smem + SM_CN);
    float* redv = (float*)(smem + SM_REDV);
    int*   redi = (int*)(smem + SM_REDI);
    int*   idxS = (int*)(smem + SM_IDX);

    const int tid  = threadIdx.x;
    const int wid  = tid >> 5;
    const int lane = tid & 31;
    const int wm   = wid & 1;        // M half: rows wm*64..
    const int wn   = wid >> 1;       // N quarter: codes wn*32.. per super-chunk
    const int tig  = lane & 3;
    const int g    = lane >> 2;
    const int row0 = blockIdx.x * ROWS_CTA;

    // precomputed ldmatrix per-lane sub-offsets
    const int arow = (lane & 7) + (((lane >> 3) & 1) << 3);   // A: row within m16
    const int acol = ((lane >> 4) << 3);                      // A: k sub-offset
    const int bcode = (lane & 7) + ((lane >> 4) << 3);        // B: code within 16
    const int bcol  = (((lane >> 3) & 1) << 3);               // B: k sub-offset

    for (int s = 0; s < NSTAGES; ++s) {
        // ---- fused residual-update + bf16 A build ----
        {
            const float* srcbase = (s <= 1) ? input : g_res;
            #pragma unroll 4
            for (int i = 0; i < 64; i++) {
                int e = tid + (i << 8);
                int r = e >> 7, p = e & 127;
                float2 v = ((const float2*)(srcbase + (size_t)(row0 + r) * DIM))[p];
                if (s > 0) {
                    int code = idxS[r];
                    float2 cv = ((const float2*)(cbf32 +
                                 ((size_t)(s - 1) * NCODES + code) * DIM))[p];
                    v.x -= cv.x; v.y -= cv.y;
                    ((float2*)(g_res + (size_t)(row0 + r) * DIM))[p] = v;
                }
                __nv_bfloat162 bb = __floats2bfloat162_rn(v.x, v.y);
                *(uint32_t*)(smem + SM_A + (((size_t)r * A_STRIDE + p * 2) << 1)) = *(uint32_t*)&bb;
            }
            for (int j = tid; j < NCODES; j += 256) cnS[j] = g_cnorm[s * NCODES + j];
        }

        cp_b(s, 0, sb + SM_B, tid);
        CP_COMMIT;

        float best[8]; int bidx[8];
        #pragma unroll
        for (int q = 0; q < 8; q++) { best[q] = INFINITY; bidx[q] = 0; }
        float acc[4][4][4];

        for (int t = 0; t < 32; t++) {
            if (t < 31) {
                cp_b(s, t + 1, sb + SM_B + ((t + 1) & 1) * B_TILE, tid);
                CP_COMMIT;
                CP_WAIT1;
            } else {
                CP_WAIT0;
            }
            __syncthreads();  // B tile ready + (t==0) A build visible

            const int nsc = t >> 2, kb = t & 3;
            if (kb == 0) {
                #pragma unroll
                for (int m = 0; m < 4; m++)
                    #pragma unroll
                    for (int n = 0; n < 4; n++)
                        #pragma unroll
                        for (int q = 0; q < 4; q++) acc[m][n][q] = 0.f;
            }
            const uint32_t bbase = sb + SM_B + (t & 1) * B_TILE;

            #pragma unroll
            for (int ks = 0; ks < 4; ks++) {
                const int kk = kb * 64 + ks * 16;
                uint32_t a[4][4];
                #pragma unroll
                for (int m = 0; m < 4; m++) {
                    uint32_t ad = sb + SM_A +
                        ((uint32_t)((wm * 64 + m * 16 + arow) * A_STRIDE + kk + acol) << 1);
                    ldmx4(a[m], ad);
                }
                uint32_t b[2][4];
                #pragma unroll
                for (int p = 0; p < 2; p++) {
                    uint32_t bd = bbase +
                        ((uint32_t)((wn * 32 + p * 16 + bcode) * B_STRIDE + ks * 16 + bcol) << 1);
                    ldmx4t(b[p], bd);
                }
                #pragma unroll
                for (int m = 0; m < 4; m++)
                    #pragma unroll
                    for (int n = 0; n < 4; n++)
                        mma16816(acc[m][n], a[m], b[n >> 1][(n & 1) * 2], b[n >> 1][(n & 1) * 2 + 1]);
            }
            __syncthreads();  // all warps done with buffers before overwrite

            if (kb == 3) {
                #pragma unroll
                for (int m = 0; m < 4; m++) {
                    #pragma unroll
                    for (int n = 0; n < 4; n++) {
                        int c0 = nsc * 128 + wn * 32 + n * 8 + tig * 2;
                        float cn0 = cnS[c0], cn1 = cnS[c0 + 1];
                        float s0 = fmaf(-2.f, acc[m][n][0], cn0);
                        float s1 = fmaf(-2.f, acc[m][n][1], cn1);
                        float s2 = fmaf(-2.f, acc[m][n][2], cn0);
                        float s3 = fmaf(-2.f, acc[m][n][3], cn1);
                        if (s0 < best[m * 2])     { best[m * 2] = s0;     bidx[m * 2] = c0; }
                        if (s1 < best[m * 2])     { best[m * 2] = s1;     bidx[m * 2] = c0 + 1; }
                        if (s2 < best[m * 2 + 1]) { best[m * 2 + 1] = s2; bidx[m * 2 + 1] = c0; }
                        if (s3 < best[m * 2 + 1]) { best[m * 2 + 1] = s3; bidx[m * 2 + 1] = c0 + 1; }
                    }
                }
            }
        }

        // ---- reduce across tig lanes (codes) ----
        #pragma unroll
        for (int q = 0; q < 8; q++) {
            float bv = best[q]; int bi = bidx[q];
            #pragma unroll
            for (int off = 1; off <= 2; off <<= 1) {
                float ov = __shfl_xor_sync(0xffffffffu, bv, off);
                int   oi = __shfl_xor_sync(0xffffffffu, bi, off);
                if (ov < bv || (ov == bv && oi < bi)) { bv = ov; bi = oi; }
            }
            best[q] = bv; bidx[q] = bi;
        }
        if (tig == 0) {
            #pragma unroll
            for (int m = 0; m < 4; m++)
                #pragma unroll
                for (int h = 0; h < 2; h++) {
                    int row = wm * 64 + m * 16 + h * 8 + g;
                    redv[wn * 128 + row] = best[m * 2 + h];
                    redi[wn * 128 + row] = bidx[m * 2 + h];
                }
        }
        __syncthreads();
        if (tid < 128) {
            float bv = INFINITY; int bi = 0;
            #pragma unroll
            for (int w2 = 0; w2 < 4; w2++) {
                float v = redv[w2 * 128 + tid];
                int   i2 = redi[w2 * 128 + tid];
                if (v < bv || (v == bv && i2 < bi)) { bv = v; bi = i2; }
            }
            idxS[tid] = bi;
            g_presence[s * NCODES + bi] = 1;
        }
        __syncthreads();
    }

    // ---- finalize (idxS = stage-7 indices; g_res = residual through stage 6) ----
    {
        const int tm = *trainp;
        for (int i = 0; i < 16; i++) {
            int r = wid * 16 + i;
            int code = idxS[r];
            const float* cb7 = cbf32 + ((size_t)7 * NCODES + code) * DIM;
            const float* rp = g_res + (size_t)(row0 + r) * DIM;
            const float* np = noise + (size_t)(row0 + r) * DIM;
            const float* ip = input + (size_t)(row0 + r) * DIM;
            float rv[8], nv[8], iv[8];
            float se = 0.f, sn = 0.f;
            #pragma unroll
            for (int t2 = 0; t2 < 8; t2++) {
                int d = lane + 32 * t2;
                rv[t2] = rp[d] - cb7[d];
                nv[t2] = np[d];
                iv[t2] = ip[d];
                se = fmaf(rv[t2], rv[t2], se);
                sn = fmaf(nv[t2], nv[t2], sn);
            }
            #pragma unroll
            for (int o = 16; o > 0; o >>= 1) {
                se += __shfl_xor_sync(0xffffffffu, se, o);
                sn += __shfl_xor_sync(0xffffffffu, sn, o);
            }
            float* op = out + (size_t)(row0 + r) * DIM;
            if (tm) {
                float f = sqrtf(se) / sqrtf(sn) + EPSF;
                #pragma unroll
                for (int t2 = 0; t2 < 8; t2++)
                    op[lane + 32 * t2] = fmaf(f, nv[t2], iv[t2]);
            } else {
                #pragma unroll
                for (int t2 = 0; t2 < 8; t2++)
                    op[lane + 32 * t2] = iv[t2] - rv[t2];
            }
        }
    }
}

// ================= launch =================
extern "C" void kernel_launch(void* const* d_in, const int* in_sizes, int n_in,
                              void* d_out, int out_size) {
    const float* input     = (const float*)d_in[0];   // [N, 256]
    const float* codebooks = (const float*)d_in[1];   // [8, 1024, 256]
    const float* noise     = (const float*)d_in[2];   // [N, 256]
    const int*   used_in   = (const int*)d_in[3];     // [8, 1024]
    const int*   train_mod = (const int*)d_in[4];     // scalar
    float* out = (float*)d_out;

    static int configured = 0;
    cudaFuncSetAttribute(rvq_main, cudaFuncAttributeMaxDynamicSharedMemorySize, SMEM_TOTAL);
    (void)configured;

    prep_kernel<<<NCODES * NSTAGES / 8, 256>>>(codebooks);
    zero_presence_kernel<<<(NSTAGES * NCODES + 255) / 256, 256>>>();

    rvq_main<<<NROWS / ROWS_CTA, 256, SMEM_TOTAL>>>(input, codebooks, noise, train_mod, out);

    if (out_size >= NROWS * DIM + NSTAGES * NCODES) {
        used_kernel<<<(NSTAGES * NCODES + 255) / 256, 256>>>(used_in, out + (size_t)NROWS * DIM);
    }
}